// round 7
// baseline (speedup 1.0000x reference)
#include <cuda_runtime.h>
#include <cuda_bf16.h>
#include <math_constants.h>

// Problem constants (fixed shapes)
#define B_   8
#define C_   21
#define H_   512
#define W_   512
#define HW_  (H_ * W_)           // 262144 = 2^18
#define HW_SHIFT 18
#define NPIX (B_ * HW_)          // 2097152
#define MAX_M 0.5f
#define S_    30.0f

#define HIST_BLOCKS 512
#define LOSS_BLOCKS (NPIX / 4 / 256)   // 2048 blocks, 4 pixels/thread

// Scratch (device globals — no allocations allowed)
__device__ int    g_parts[HIST_BLOCKS][C_];  // per-block histogram partials
__device__ float  g_mlist[C_];
__device__ double g_loss;
__device__ unsigned int g_done;

// ---------------------------------------------------------------------------
// Kernel 1: per-block label histograms (per-warp smem sub-histograms).
// Block 0 also zeroes g_loss / g_done (consumed only by the strictly-later
// loss kernel, so this is deterministic and race-free under graph replay).
// ---------------------------------------------------------------------------
__global__ __launch_bounds__(256) void hist_kernel(const int* __restrict__ target) {
    __shared__ int sh[8][C_];
    int wid = threadIdx.x >> 5;
    for (int i = threadIdx.x; i < 8 * C_; i += 256)
        (&sh[0][0])[i] = 0;
    if (blockIdx.x == 0 && threadIdx.x == 0) { g_loss = 0.0; g_done = 0u; }
    __syncthreads();

    const int4* t4 = reinterpret_cast<const int4*>(target);
    int n4 = NPIX / 4;
    for (int i = blockIdx.x * blockDim.x + threadIdx.x; i < n4;
         i += gridDim.x * blockDim.x) {
        int4 v = t4[i];
        atomicAdd(&sh[wid][v.x], 1);
        atomicAdd(&sh[wid][v.y], 1);
        atomicAdd(&sh[wid][v.z], 1);
        atomicAdd(&sh[wid][v.w], 1);
    }
    __syncthreads();
    if (threadIdx.x < C_) {
        int s = 0;
#pragma unroll
        for (int w = 0; w < 8; w++) s += sh[w][threadIdx.x];
        g_parts[blockIdx.x][threadIdx.x] = s;
    }
}

// ---------------------------------------------------------------------------
// Kernel 2: reduce partials -> counts -> m_list  (21 warps; warp w owns class w)
// ---------------------------------------------------------------------------
__global__ void mlist_kernel() {
    __shared__ float cnt[C_];
    int w    = threadIdx.x >> 5;   // 0..20
    int lane = threadIdx.x & 31;

    int s = 0;
    for (int p = lane; p < HIST_BLOCKS; p += 32) s += g_parts[p][w];
#pragma unroll
    for (int o = 16; o > 0; o >>= 1) s += __shfl_xor_sync(0xffffffffu, s, o);
    if (lane == 0) cnt[w] = (float)s;
    __syncthreads();

    if (w == 0) {
        float mi = 0.0f, m = -CUDART_INF_F;
        if (lane < C_) {
            mi = rsqrtf(sqrtf(cnt[lane] + 1e-4f));
            m  = mi;
        }
#pragma unroll
        for (int o = 16; o > 0; o >>= 1)
            m = fmaxf(m, __shfl_xor_sync(0xffffffffu, m, o));
        if (lane < C_) g_mlist[lane] = mi * (MAX_M / m);
    }
}

// ---------------------------------------------------------------------------
// Kernel 3: LDAM NLL, 4 pixels/thread (float4), TWO PASSES over the channel
// data. Pass A computes only the running max (no per-channel storage -> low
// registers, high occupancy). Pass B re-reads the same lines — the warp's
// working set (~10 KB) is resident in L1, so DRAM traffic is unchanged —
// and accumulates the exp sum. Margin is an epilogue correction:
//   stabilizer = raw max (>= margined max, exp args <= 0, target term
//   >= exp(-S*MAX_M) = exp(-15), no over/underflow);
//   s = max(s_raw - e_l, 0) + e_{l-m}  (fmax guards cancellation).
// Finalize is fused via a fenced last-block-done counter.
// ---------------------------------------------------------------------------
__device__ __forceinline__ float pixel_nll(const float* __restrict__ p_lx,
                                           int l, float maxv, float s_raw) {
    float m   = g_mlist[l];
    float xl  = __ldg(p_lx);                     // L1 hit (line just streamed)
    float el  = __expf(S_ * (xl - maxv));
    float elm = __expf(S_ * (xl - m - maxv));
    float s   = fmaxf(s_raw - el, 0.0f) + elm;
    return __logf(s) + S_ * (maxv - (xl - m));
}

__global__ __launch_bounds__(256) void loss_kernel(const float* __restrict__ pred,
                                                   const int*   __restrict__ target,
                                                   float*       __restrict__ out) {
    int t    = blockIdx.x * 256 + threadIdx.x;
    int pix0 = t * 4;                       // 4 consecutive pixels, same batch
    int b    = pix0 >> HW_SHIFT;
    int hw   = pix0 & (HW_ - 1);
    const float*  base  = pred + (size_t)(b * C_) * HW_ + hw;
    const float4* base4 = reinterpret_cast<const float4*>(base);
    const int     cs4   = HW_ / 4;          // channel stride in float4

    // Pass A: running max only
    float4 mx = make_float4(-CUDART_INF_F, -CUDART_INF_F,
                            -CUDART_INF_F, -CUDART_INF_F);
#pragma unroll
    for (int c = 0; c < C_; c++) {
        float4 x = __ldg(base4 + c * cs4);
        mx.x = fmaxf(mx.x, x.x);
        mx.y = fmaxf(mx.y, x.y);
        mx.z = fmaxf(mx.z, x.z);
        mx.w = fmaxf(mx.w, x.w);
    }

    // Pass B: exp-sum against the known max (re-read, L1 resident)
    float4 s = make_float4(0.f, 0.f, 0.f, 0.f);
#pragma unroll
    for (int c = 0; c < C_; c++) {
        float4 x = __ldg(base4 + c * cs4);
        s.x += __expf(S_ * (x.x - mx.x));
        s.y += __expf(S_ * (x.y - mx.y));
        s.z += __expf(S_ * (x.z - mx.z));
        s.w += __expf(S_ * (x.w - mx.w));
    }

    int4 lab = __ldg(reinterpret_cast<const int4*>(target + pix0));

    float nll = pixel_nll(base + (size_t)lab.x * HW_ + 0, lab.x, mx.x, s.x)
              + pixel_nll(base + (size_t)lab.y * HW_ + 1, lab.y, mx.y, s.y)
              + pixel_nll(base + (size_t)lab.z * HW_ + 2, lab.z, mx.z, s.z)
              + pixel_nll(base + (size_t)lab.w * HW_ + 3, lab.w, mx.w, s.w);

    // Warp reduce, cross-warp via smem, one f64 atomic per block.
#pragma unroll
    for (int o = 16; o > 0; o >>= 1)
        nll += __shfl_xor_sync(0xffffffffu, nll, o);

    __shared__ float warp_sums[8];
    int lane = threadIdx.x & 31;
    int wid  = threadIdx.x >> 5;
    if (lane == 0) warp_sums[wid] = nll;
    __syncthreads();

    if (wid == 0) {
        float x = (lane < 8) ? warp_sums[lane] : 0.0f;
#pragma unroll
        for (int o = 4; o > 0; o >>= 1)
            x += __shfl_xor_sync(0xffffffffu, x, o);
        if (lane == 0) {
            atomicAdd(&g_loss, (double)x);
            __threadfence();
            unsigned int done = atomicAdd(&g_done, 1u);
            if (done == (unsigned int)(gridDim.x - 1)) {
                // All blocks' g_loss atomics are globally visible (each block
                // fenced between its loss-add and its done-increment).
                double total = atomicAdd(&g_loss, 0.0);
                out[0] = (float)(total * (1.0 / (double)NPIX));
            }
        }
    }
}

// ---------------------------------------------------------------------------
extern "C" void kernel_launch(void* const* d_in, const int* in_sizes, int n_in,
                              void* d_out, int out_size) {
    const float* pred   = (const float*)d_in[0];
    const int*   target = (const int*)d_in[1];
    float*       out    = (float*)d_out;

    hist_kernel<<<HIST_BLOCKS, 256>>>(target);
    mlist_kernel<<<1, C_ * 32>>>();
    loss_kernel<<<LOSS_BLOCKS, 256>>>(pred, target, out);
}

// round 8
// speedup vs baseline: 1.1871x; 1.1871x over previous
#include <cuda_runtime.h>
#include <cuda_bf16.h>
#include <math_constants.h>

// Problem constants (fixed shapes)
#define B_   8
#define C_   21
#define H_   512
#define W_   512
#define HW_  (H_ * W_)           // 262144 = 2^18
#define HW_SHIFT 18
#define NPIX (B_ * HW_)          // 2097152
#define MAX_M 0.5f
#define S_    30.0f

#define HIST_BLOCKS (NPIX / 4 / 256)   // 2048: one int4 per thread, no loop
#define LOSS_BLOCKS (NPIX / 256)       // 8192: one pixel per thread

// Scratch (device globals — no allocations allowed)
__device__ int          g_parts[HIST_BLOCKS][C_];  // per-block histogram partials
__device__ float        g_mlist[C_];
__device__ double       g_loss;
__device__ unsigned int g_done;

// ---------------------------------------------------------------------------
// Kernel 1: per-block label histograms, one int4 per thread (full occupancy).
// Block 0 also zeroes g_loss / g_done (consumed only by the strictly-later
// loss kernel on the same stream, so deterministic under graph replay).
// ---------------------------------------------------------------------------
__global__ __launch_bounds__(256) void hist_kernel(const int* __restrict__ target) {
    __shared__ int sh[8][C_];
    int wid = threadIdx.x >> 5;
    for (int i = threadIdx.x; i < 8 * C_; i += 256)
        (&sh[0][0])[i] = 0;
    if (blockIdx.x == 0 && threadIdx.x == 0) { g_loss = 0.0; g_done = 0u; }
    __syncthreads();

    int4 v = reinterpret_cast<const int4*>(target)[blockIdx.x * 256 + threadIdx.x];
    atomicAdd(&sh[wid][v.x], 1);
    atomicAdd(&sh[wid][v.y], 1);
    atomicAdd(&sh[wid][v.z], 1);
    atomicAdd(&sh[wid][v.w], 1);
    __syncthreads();

    if (threadIdx.x < C_) {
        int s = 0;
#pragma unroll
        for (int w = 0; w < 8; w++) s += sh[w][threadIdx.x];
        g_parts[blockIdx.x][threadIdx.x] = s;
    }
}

// ---------------------------------------------------------------------------
// Kernel 2: reduce partials -> counts -> m_list  (21 warps; warp w owns class w)
// ---------------------------------------------------------------------------
__global__ void mlist_kernel() {
    __shared__ float cnt[C_];
    int w    = threadIdx.x >> 5;   // 0..20
    int lane = threadIdx.x & 31;

    int s = 0;
    for (int p = lane; p < HIST_BLOCKS; p += 32) s += g_parts[p][w];
#pragma unroll
    for (int o = 16; o > 0; o >>= 1) s += __shfl_xor_sync(0xffffffffu, s, o);
    if (lane == 0) cnt[w] = (float)s;
    __syncthreads();

    if (w == 0) {
        float mi = 0.0f, m = -CUDART_INF_F;
        if (lane < C_) {
            mi = rsqrtf(sqrtf(cnt[lane] + 1e-4f));
            m  = mi;
        }
#pragma unroll
        for (int o = 16; o > 0; o >>= 1)
            m = fmaxf(m, __shfl_xor_sync(0xffffffffu, m, o));
        if (lane < C_) g_mlist[lane] = mi * (MAX_M / m);
    }
}

// ---------------------------------------------------------------------------
// Kernel 3: LDAM NLL, 1 pixel/thread, single pass (proven R3 body), margin
// handled as an epilogue correction so the hot per-channel loop is pure
// LDG + FMAX + exp-accumulate (no per-channel compares/selects).
//
// Stabilizer = raw channel max (>= margined max): all exp args <= 0 and the
// surviving target term >= exp(-S*MAX_M) = exp(-15) -> no over/underflow.
// Patch: s = max(s_raw - e_l, 0) + e_{l-m}; fmax guards float cancellation.
// x_l is re-read via __ldg — the line was loaded by this warp microseconds
// ago and 256 B/warp of reload is negligible even on an L1 miss.
// Finalize fused via fenced done-counter (proven in R7).
// ---------------------------------------------------------------------------
__global__ __launch_bounds__(256) void loss_kernel(const float* __restrict__ pred,
                                                   const int*   __restrict__ target,
                                                   float*       __restrict__ out) {
    int n  = blockIdx.x * 256 + threadIdx.x;   // exact grid: n < NPIX
    int b  = n >> HW_SHIFT;
    int hw = n & (HW_ - 1);
    const float* base = pred + (size_t)(b * C_) * HW_ + hw;

    // Single pass: store channel values, track running max (no compares).
    float v[C_];
    float maxv = -CUDART_INF_F;
#pragma unroll
    for (int c = 0; c < C_; c++) {
        float x = __ldg(base + (size_t)c * HW_);
        v[c] = x;
        maxv = fmaxf(maxv, x);
    }

    float s = 0.0f;
#pragma unroll
    for (int c = 0; c < C_; c++)
        s += __expf(S_ * (v[c] - maxv));

    // Epilogue: margin correction at the target class only.
    int   l   = target[n];
    float m   = g_mlist[l];
    float xl  = __ldg(base + (size_t)l * HW_);
    float el  = __expf(S_ * (xl - maxv));
    float elm = __expf(S_ * (xl - m - maxv));
    float sp  = fmaxf(s - el, 0.0f) + elm;
    float nll = __logf(sp) + S_ * (maxv - (xl - m));

    // Warp reduce, cross-warp via smem, one f64 atomic per block.
#pragma unroll
    for (int o = 16; o > 0; o >>= 1)
        nll += __shfl_xor_sync(0xffffffffu, nll, o);

    __shared__ float warp_sums[8];
    int lane = threadIdx.x & 31;
    int wid  = threadIdx.x >> 5;
    if (lane == 0) warp_sums[wid] = nll;
    __syncthreads();

    if (wid == 0) {
        float x = (lane < 8) ? warp_sums[lane] : 0.0f;
#pragma unroll
        for (int o = 4; o > 0; o >>= 1)
            x += __shfl_xor_sync(0xffffffffu, x, o);
        if (lane == 0) {
            atomicAdd(&g_loss, (double)x);
            __threadfence();
            unsigned int done = atomicAdd(&g_done, 1u);
            if (done == (unsigned int)(gridDim.x - 1)) {
                double total = atomicAdd(&g_loss, 0.0);
                out[0] = (float)(total * (1.0 / (double)NPIX));
            }
        }
    }
}

// ---------------------------------------------------------------------------
extern "C" void kernel_launch(void* const* d_in, const int* in_sizes, int n_in,
                              void* d_out, int out_size) {
    const float* pred   = (const float*)d_in[0];
    const int*   target = (const int*)d_in[1];
    float*       out    = (float*)d_out;

    hist_kernel<<<HIST_BLOCKS, 256>>>(target);
    mlist_kernel<<<1, C_ * 32>>>();
    loss_kernel<<<LOSS_BLOCKS, 256>>>(pred, target, out);
}